// round 10
// baseline (speedup 1.0000x reference)
#include <cuda_runtime.h>
#include <cuda_fp16.h>
#include <cstdint>

#define NUM_A 8
#define EDIM 128
#define OUTSTRIDE (NUM_A * EDIM)   // 1024 floats per batch row of edge/out
#define KC 32                      // K elements per pipeline chunk
#define NCHUNK 8                   // total K = 256 (128 img + 128 edge)
#define NSTAGE 4
#define MTILE 128
#define THREADS 256                // 8 warps, each owning a 32x64 output tile
#define A_BYTES (MTILE * KC * 4)           // 16 KB fp32 A tile (SW128 rows)
#define B_BYTES (EDIM * KC * 2)            // 8 KB fp16 B tile (64B rows)
#define STAGE_BYTES (A_BYTES + B_BYTES)    // 24 KB

// Precomputed fused weights in fp16 (n-major rows, k contiguous) + fp32 bias-via-proj.
__device__ __half g_P1h[NUM_A * EDIM * EDIM];  // [a][j][k] = sum_i W[i,k]   * proj[a,i,j]
__device__ __half g_P2h[NUM_A * EDIM * EDIM];  // [a][j][k] = sum_i W[i,E+k] * proj[a,i,j]
__device__ float  g_cvec[NUM_A * EDIM];        // [a][j]    = sum_i b[i]     * proj[a,i,j]

__device__ __forceinline__ uint32_t swz(uint32_t x) { return x ^ ((x >> 3) & 0x70u); }

__device__ __forceinline__ void cp_async16(uint32_t dst, const void* src) {
    asm volatile("cp.async.cg.shared.global [%0], [%1], 16;" :: "r"(dst), "l"(src));
}
__device__ __forceinline__ void cp_commit() { asm volatile("cp.async.commit_group;"); }
template <int N> __device__ __forceinline__ void cp_wait() {
    asm volatile("cp.async.wait_group %0;" :: "n"(N));
}
__device__ __forceinline__ void ldsm_x4(uint32_t& r0, uint32_t& r1, uint32_t& r2, uint32_t& r3,
                                        uint32_t addr) {
    asm volatile("ldmatrix.sync.aligned.m8n8.x4.shared.b16 {%0,%1,%2,%3}, [%4];"
                 : "=r"(r0), "=r"(r1), "=r"(r2), "=r"(r3) : "r"(addr));
}
// pack {lo=f0, hi=f1} into one fp16x2 register
__device__ __forceinline__ uint32_t f16x2(float f0, float f1) {
    uint32_t d;
    asm("cvt.rn.f16x2.f32 %0, %1, %2;" : "=r"(d) : "f"(f1), "f"(f0));
    return d;
}
__device__ __forceinline__ void lds64(float& x, float& y, uint32_t addr) {
    asm volatile("ld.shared.v2.f32 {%0,%1}, [%2];" : "=f"(x), "=f"(y) : "r"(addr));
}
__device__ __forceinline__ void mma_f16(float* c, const uint32_t* a, uint32_t b0, uint32_t b1) {
    asm volatile("mma.sync.aligned.m16n8k16.row.col.f32.f16.f16.f32 "
                 "{%0,%1,%2,%3},{%4,%5,%6,%7},{%8,%9},{%0,%1,%2,%3};"
                 : "+f"(c[0]), "+f"(c[1]), "+f"(c[2]), "+f"(c[3])
                 : "r"(a[0]), "r"(a[1]), "r"(a[2]), "r"(a[3]), "r"(b0), "r"(b1));
}

// fp16 B-tile swizzle: 64B rows (32 fp16), 4x16B chunks; chunk index XORed with
// (row>>1)&3 so the 8 rows of every ldmatrix 8x8 block hit distinct bank groups.
__device__ __forceinline__ uint32_t b_off(int row, int cbyte) {
    return (uint32_t)(row * 64 + ((((cbyte >> 4) ^ ((row >> 1) & 3)) << 4) | (cbyte & 15)));
}

// ---------------------------------------------------------------------------
// Precompute fused weights (fp16) and cvec. 67 MFLOP, negligible.
// ---------------------------------------------------------------------------
__global__ void precompute_kernel(const float* __restrict__ W, const float* __restrict__ bvec,
                                  const float* __restrict__ proj) {
    const int a = blockIdx.x;
    const int j = blockIdx.y;
    const int k = threadIdx.x;
    const float* pa = proj + ((size_t)a * EDIM) * EDIM + j;   // proj[a][i][j], stride E
    float acc1 = 0.f, acc2 = 0.f, accC = 0.f;
#pragma unroll 8
    for (int i = 0; i < EDIM; i++) {
        float p = __ldg(pa + (size_t)i * EDIM);
        acc1 = fmaf(__ldg(W + i * 2 * EDIM + k), p, acc1);
        acc2 = fmaf(__ldg(W + i * 2 * EDIM + EDIM + k), p, acc2);
        accC = fmaf(__ldg(bvec + i), p, accC);
    }
    size_t o = ((size_t)a * EDIM + j) * EDIM + k;
    g_P1h[o] = __float2half_rn(acc1);
    g_P2h[o] = __float2half_rn(acc2);
    if (k == 0) g_cvec[a * EDIM + j] = accC;
}

// ---------------------------------------------------------------------------
// Fused GEMM, fp16 mma, DEEP pipeline: 4 stages, loads issued 3 chunks ahead,
// cp.async.wait_group 2 -> two full compute phases of latency slack per load
// group (targets the measured chunk-convoy stall that froze rounds 7-9 at
// ~151us). CTA = (a, 128-row m-tile), 8 warps x 32x64 tiles, 2 CTAs/SM.
// A fp32 in smem (SW128), fragments via LDS.64 + cvt f16x2 (round-7 path);
// B fp16 precomputed weights via cp.async.
// ---------------------------------------------------------------------------
__global__ __launch_bounds__(THREADS, 2) void gnn_kernel(const float* __restrict__ img,
                                                         const float* __restrict__ edge,
                                                         float* __restrict__ out) {
    extern __shared__ float smem[];
    const uint32_t smem_b = (uint32_t)__cvta_generic_to_shared(smem);
    const int a = blockIdx.x;
    const int mbase = blockIdx.y * MTILE;
    const int tid = threadIdx.x;
    const int lane = tid & 31;
    const int warp = tid >> 5;
    const int m0 = (warp & 3) * 32;    // warp row base within CTA tile
    const int n0 = (warp >> 2) * 64;   // warp col base within CTA tile

    float acc[2][8][4];
#pragma unroll
    for (int mt = 0; mt < 2; mt++)
#pragma unroll
        for (int nt = 0; nt < 8; nt++)
#pragma unroll
            for (int v = 0; v < 4; v++) acc[mt][nt][v] = 0.f;

    auto load_chunk = [&](int kc, int s) {
        const uint32_t abase = smem_b + s * STAGE_BYTES;
        const uint32_t bbase = abase + A_BYTES;
        const float* srcA;
        size_t strideA;
        if (kc < 4) { srcA = img + (size_t)mbase * EDIM + kc * KC;                     strideA = EDIM; }
        else        { srcA = edge + (size_t)mbase * OUTSTRIDE + a * EDIM + (kc - 4) * KC; strideA = OUTSTRIDE; }
        const __half* Ph = (kc < 4) ? g_P1h : g_P2h;
        const __half* srcB = Ph + ((size_t)a * EDIM) * EDIM + (kc & 3) * KC;
        // A: 16KB fp32, SW128 rows of 128B
#pragma unroll
        for (int q = 0; q < 4; q++) {
            int id = tid + q * THREADS;   // 0..1023
            int row = id >> 3;
            int c4 = id & 7;
            cp_async16(abase + swz((uint32_t)(row * 128 + c4 * 16)),
                       srcA + (size_t)row * strideA + c4 * 4);
        }
        // B: 8KB fp16, 64B rows with b_off swizzle (512 x 16B)
#pragma unroll
        for (int q = 0; q < 2; q++) {
            int id = tid + q * THREADS;   // 0..511
            int j = id >> 2;
            int c16 = id & 3;
            cp_async16(bbase + b_off(j, c16 * 16), srcB + (size_t)j * EDIM + c16 * 8);
        }
        cp_commit();
    };

    auto compute_chunk = [&](int s) {
        const uint32_t abase = smem_b + s * STAGE_BYTES;
        const uint32_t bbase = abase + A_BYTES;
#pragma unroll
        for (int ks = 0; ks < 2; ks++) {   // 2 k16 steps per 32-wide chunk
            // A fragments: fp32 LDS.64 pairs -> fp16x2
            uint32_t afr[2][4];
#pragma unroll
            for (int mt = 0; mt < 2; mt++) {
                int r = m0 + mt * 16 + (lane >> 2);
                uint32_t kb = (uint32_t)(ks * 64 + (lane & 3) * 8);   // byte offset of k pair
                uint32_t ad0 = abase + r * 128 + (kb ^ (uint32_t)((r & 7) << 4));
                uint32_t ad1 = abase + (r + 8) * 128 + (kb ^ (uint32_t)(((r + 8) & 7) << 4));
                float x0, y0, x1, y1, x2, y2, x3, y3;
                lds64(x0, y0, ad0);          // (r,   k..k+1)
                lds64(x1, y1, ad1);          // (r+8, k..k+1)
                lds64(x2, y2, ad0 ^ 32u);    // (r,   k+8..k+9)
                lds64(x3, y3, ad1 ^ 32u);    // (r+8, k+8..k+9)
                afr[mt][0] = f16x2(x0, y0);
                afr[mt][1] = f16x2(x1, y1);
                afr[mt][2] = f16x2(x2, y2);
                afr[mt][3] = f16x2(x3, y3);
            }
            // B fragments: ldmatrix.x4 per 16-col group
#pragma unroll
            for (int ng = 0; ng < 4; ng++) {
                int blk = lane >> 3;                       // 0..3
                int jr = n0 + ng * 16 + (lane & 7) + ((blk & 2) ? 8 : 0);
                int cB = ks * 32 + (blk & 1) * 16;
                uint32_t r0, r1, r2, r3;
                ldsm_x4(r0, r1, r2, r3, bbase + b_off(jr, cB));
#pragma unroll
                for (int mt = 0; mt < 2; mt++) {
                    mma_f16(acc[mt][ng * 2],     afr[mt], r0, r1);
                    mma_f16(acc[mt][ng * 2 + 1], afr[mt], r2, r3);
                }
            }
        }
    };

    // Deep pipeline: preload chunks 0,1,2. Each iteration: wait for chunk kc
    // (leaving 2 newer groups in flight), barrier, issue load kc+3 into the
    // stage all warps finished at compute kc-1, compute kc.
    load_chunk(0, 0);
    load_chunk(1, 1);
    load_chunk(2, 2);
#pragma unroll 1
    for (int kc = 0; kc < NCHUNK; kc++) {
        if (kc < NCHUNK - 2)      { cp_wait<2>(); }
        else if (kc == NCHUNK - 2){ cp_wait<1>(); }
        else                      { cp_wait<0>(); }
        __syncthreads();
        if (kc + 3 < NCHUNK) load_chunk(kc + 3, (kc + 3) % NSTAGE);
        compute_chunk(kc % NSTAGE);
    }

    // Epilogue: add bias-through-projection, store float2 pairs.
    const float* cv = g_cvec + a * EDIM;
#pragma unroll
    for (int mt = 0; mt < 2; mt++) {
        int r0 = mbase + m0 + mt * 16 + (lane >> 2);
#pragma unroll
        for (int nt = 0; nt < 8; nt++) {
            int col = n0 + (nt >> 1) * 16 + (nt & 1) * 8 + (lane & 3) * 2;
            float b0 = __ldg(cv + col);
            float b1 = __ldg(cv + col + 1);
            float2 v0 = make_float2(acc[mt][nt][0] + b0, acc[mt][nt][1] + b1);
            float2 v1 = make_float2(acc[mt][nt][2] + b0, acc[mt][nt][3] + b1);
            size_t base0 = (size_t)r0 * OUTSTRIDE + a * EDIM + col;
            size_t base1 = (size_t)(r0 + 8) * OUTSTRIDE + a * EDIM + col;
            *reinterpret_cast<float2*>(out + base0) = v0;
            *reinterpret_cast<float2*>(out + base1) = v1;
        }
    }
}

extern "C" void kernel_launch(void* const* d_in, const int* in_sizes, int n_in,
                              void* d_out, int out_size) {
    const float* img  = (const float*)d_in[0];   // [B, E]
    const float* edge = (const float*)d_in[1];   // [B, A, E]
    const float* W    = (const float*)d_in[2];   // [E, 2E]
    const float* bvec = (const float*)d_in[3];   // [E]
    const float* proj = (const float*)d_in[4];   // [A, E, E]
    const int Bn = in_sizes[0] / EDIM;

    precompute_kernel<<<dim3(NUM_A, EDIM), EDIM>>>(W, bvec, proj);

    cudaFuncSetAttribute(gnn_kernel, cudaFuncAttributeMaxDynamicSharedMemorySize,
                         NSTAGE * STAGE_BYTES);
    // blockIdx.x = a (fast dim) so the 8 a-CTAs of one m-tile run adjacently:
    // img tile and the contiguous edge row block get full L2 reuse.
    gnn_kernel<<<dim3(NUM_A, Bn / MTILE), THREADS, NSTAGE * STAGE_BYTES>>>(
        img, edge, (float*)d_out);
}

// round 11
// speedup vs baseline: 1.1021x; 1.1021x over previous
#include <cuda_runtime.h>
#include <cuda_fp16.h>
#include <cstdint>

#define NUM_A 8
#define EDIM 128
#define OUTSTRIDE (NUM_A * EDIM)   // 1024 floats per batch row of edge/out
#define KC 32                      // K elements per pipeline chunk
#define CHPT 8                     // chunks per tile (K = 256)
#define NSTAGE 3
#define MTILE 128
#define THREADS 256                // 8 warps, each owning a 32x64 output tile
#define A_BYTES (MTILE * KC * 2)   // 8 KB fp16 A stage (128 rows x 64B)
#define B_RES_BYTES (EDIM * 256 * 2)       // 64 KB resident fused-weight tile
#define SMEM_TOTAL (B_RES_BYTES + NSTAGE * A_BYTES)   // 88 KB

// Fused weights fp16, combined K: g_Ph[a][j][k], k<128 img half, k>=128 edge half.
__device__ __half g_Ph[NUM_A * EDIM * 256];
__device__ float  g_cvec[NUM_A * EDIM];    // bias through projection

__device__ __forceinline__ void cp_async16(uint32_t dst, const void* src) {
    asm volatile("cp.async.cg.shared.global [%0], [%1], 16;" :: "r"(dst), "l"(src));
}
__device__ __forceinline__ void cp_commit() { asm volatile("cp.async.commit_group;"); }
__device__ __forceinline__ void cp_wait0() {
    asm volatile("cp.async.wait_group 0;");
}
__device__ __forceinline__ void ldsm_x4(uint32_t& r0, uint32_t& r1, uint32_t& r2, uint32_t& r3,
                                        uint32_t addr) {
    asm volatile("ldmatrix.sync.aligned.m8n8.x4.shared.b16 {%0,%1,%2,%3}, [%4];"
                 : "=r"(r0), "=r"(r1), "=r"(r2), "=r"(r3) : "r"(addr));
}
__device__ __forceinline__ uint32_t f16x2(float f0, float f1) {
    uint32_t d;
    asm("cvt.rn.f16x2.f32 %0, %1, %2;" : "=r"(d) : "f"(f1), "f"(f0));
    return d;
}
__device__ __forceinline__ void sts64(uint32_t addr, uint32_t r0, uint32_t r1) {
    asm volatile("st.shared.v2.b32 [%0], {%1,%2};" :: "r"(addr), "r"(r0), "r"(r1));
}
__device__ __forceinline__ void mma_f16(float* c, const uint32_t* a, uint32_t b0, uint32_t b1) {
    asm volatile("mma.sync.aligned.m16n8k16.row.col.f32.f16.f16.f32 "
                 "{%0,%1,%2,%3},{%4,%5,%6,%7},{%8,%9},{%0,%1,%2,%3};"
                 : "+f"(c[0]), "+f"(c[1]), "+f"(c[2]), "+f"(c[3])
                 : "r"(a[0]), "r"(a[1]), "r"(a[2]), "r"(a[3]), "r"(b0), "r"(b1));
}

// A-stage swizzle: 64B rows (32 fp16), 4x16B chunks; chunk XOR (row>>1)&3.
__device__ __forceinline__ uint32_t a_off(int row, int cbyte) {
    return (uint32_t)(row * 64 + ((((cbyte >> 4) ^ ((row >> 1) & 3)) << 4) | (cbyte & 15)));
}
// Resident-B swizzle: 512B rows (256 fp16), 32x16B chunks; chunk low3 XOR (j&7)
// -> 8 consecutive j rows at the same chunk hit 8 distinct bank groups.
__device__ __forceinline__ uint32_t b_off(int j, int c16) {
    return (uint32_t)(j * 512 + (((c16 & ~7) | ((c16 ^ j) & 7)) << 4));
}

// ---------------------------------------------------------------------------
// Precompute fused weights (fp16, combined K) and cvec. 67 MFLOP, negligible.
// k < 128: img half (W[:, k]); k >= 128: edge half (W[:, k]).
// ---------------------------------------------------------------------------
__global__ void precompute_kernel(const float* __restrict__ W, const float* __restrict__ bvec,
                                  const float* __restrict__ proj) {
    const int a = blockIdx.x;
    const int j = blockIdx.y;
    const int k = threadIdx.x;   // 0..255
    const float* pa = proj + ((size_t)a * EDIM) * EDIM + j;   // proj[a][i][j], stride E
    float acc = 0.f, accC = 0.f;
#pragma unroll 8
    for (int i = 0; i < EDIM; i++) {
        float p = __ldg(pa + (size_t)i * EDIM);
        acc = fmaf(__ldg(W + i * 256 + k), p, acc);
        if (k == 0) accC = fmaf(__ldg(bvec + i), p, accC);
    }
    g_Ph[((size_t)a * EDIM + j) * 256 + k] = __float2half_rn(acc);
    if (k == 0) g_cvec[a * EDIM + j] = accC;
}

// ---------------------------------------------------------------------------
// RESIDENT-B persistent GEMM. CTA = (a, slot); loads B[a] (64KB fp16) into smem
// ONCE, then loops over m-tiles (slot, slot+nslot, ...). Main loop has NO
// cp.async: A streams LDG fp32 -> cvt f16x2 -> STS fp16 (3-stage ring, rolled
// across tile boundaries), B fragments ldsm from the resident tile.
// Cuts B L2 reads 256MB -> 19MB. 8 warps x 32x64 tiles, 2 CTAs/SM.
// ---------------------------------------------------------------------------
__global__ __launch_bounds__(THREADS, 2) void gnn_kernel(const float* __restrict__ img,
                                                         const float* __restrict__ edge,
                                                         float* __restrict__ out,
                                                         int ntiles_m) {
    extern __shared__ float smem[];
    const uint32_t smem_b = (uint32_t)__cvta_generic_to_shared(smem);
    const uint32_t bres = smem_b;                       // resident B
    const uint32_t astg = smem_b + B_RES_BYTES;         // A ring
    const int a = blockIdx.x;
    const int slot = blockIdx.y;
    const int nslot = gridDim.y;
    const int tid = threadIdx.x;
    const int lane = tid & 31;
    const int warp = tid >> 5;
    const int m0 = (warp & 3) * 32;    // warp row base within CTA tile
    const int n0 = (warp >> 2) * 64;   // warp col base within CTA tile

    // ---- Prologue: load resident B[a] (64KB) via cp.async ----
    {
        const __half* srcB = g_Ph + (size_t)a * EDIM * 256;
#pragma unroll
        for (int q = 0; q < 16; q++) {
            int id = tid + q * THREADS;    // 0..4095
            int j = id >> 5;
            int c16 = id & 31;
            cp_async16(bres + b_off(j, c16), srcB + (size_t)j * 256 + c16 * 8);
        }
        cp_commit();
    }

    const int my_tiles = (ntiles_m - slot + nslot - 1) / nslot;
    if (my_tiles <= 0) { cp_wait0(); return; }
    const int total_chunks = my_tiles * CHPT;

    float acc[2][8][4];
#pragma unroll
    for (int mt = 0; mt < 2; mt++)
#pragma unroll
        for (int nt = 0; nt < 8; nt++)
#pragma unroll
            for (int v = 0; v < 4; v++) acc[mt][nt][v] = 0.f;

    float4 regA[4];

    // LDG one A chunk (global chunk index g): tile = slot + (g/8)*nslot.
    auto ldg_chunk = [&](int g) {
        const int mbase = (slot + (g >> 3) * nslot) * MTILE;
        const int kc = g & 7;
        const float* srcA;
        size_t strideA;
        if (kc < 4) { srcA = img + (size_t)mbase * EDIM + kc * KC;                     strideA = EDIM; }
        else        { srcA = edge + (size_t)mbase * OUTSTRIDE + a * EDIM + (kc - 4) * KC; strideA = OUTSTRIDE; }
        const int c4 = tid & 7;
        const int r0 = tid >> 3;
#pragma unroll
        for (int q = 0; q < 4; q++)
            regA[q] = *reinterpret_cast<const float4*>(srcA + (size_t)(r0 + 32 * q) * strideA + c4 * 4);
    };

    auto sts_chunk = [&](int s) {
        const uint32_t abase = astg + s * A_BYTES;
        const int c4 = tid & 7;
        const int r0 = tid >> 3;
#pragma unroll
        for (int q = 0; q < 4; q++) {
            uint32_t p0 = f16x2(regA[q].x, regA[q].y);
            uint32_t p1 = f16x2(regA[q].z, regA[q].w);
            sts64(abase + a_off(r0 + 32 * q, c4 * 8), p0, p1);
        }
    };

    auto compute_chunk = [&](int s, int kc) {
        const uint32_t abase = astg + s * A_BYTES;
#pragma unroll
        for (int ks = 0; ks < 2; ks++) {   // 2 k16 steps per 32-wide chunk
            uint32_t afr[2][4];
#pragma unroll
            for (int mt = 0; mt < 2; mt++) {
                int r = m0 + mt * 16 + (lane & 15);
                int cb = ks * 32 + (lane >> 4) * 16;
                ldsm_x4(afr[mt][0], afr[mt][1], afr[mt][2], afr[mt][3],
                        abase + a_off(r, cb));
            }
#pragma unroll
            for (int ng = 0; ng < 4; ng++) {
                int blk = lane >> 3;                       // 0..3
                int jr = n0 + ng * 16 + (lane & 7) + ((blk & 2) ? 8 : 0);
                int c16 = kc * 4 + ks * 2 + (blk & 1);     // 16B chunk within 512B row
                uint32_t r0, r1, r2, r3;
                ldsm_x4(r0, r1, r2, r3, bres + b_off(jr, c16));
#pragma unroll
                for (int mt = 0; mt < 2; mt++) {
                    mma_f16(acc[mt][ng * 2],     afr[mt], r0, r1);
                    mma_f16(acc[mt][ng * 2 + 1], afr[mt], r2, r3);
                }
            }
        }
    };

    // Prologue of the A ring: chunk0 -> regs; B wait; chunk0 -> smem; chunk1 -> regs.
    ldg_chunk(0);
    cp_wait0();                      // resident B landed
    sts_chunk(0);
    if (total_chunks > 1) ldg_chunk(1);

#pragma unroll 1
    for (int g = 0; g < total_chunks; g++) {
        __syncthreads();             // A stage g (STS'd last iter) visible
        compute_chunk(g % NSTAGE, g & 7);
        if (g + 1 < total_chunks) sts_chunk((g + 1) % NSTAGE);
        if (g + 2 < total_chunks) ldg_chunk(g + 2);

        if ((g & 7) == 7) {
            // Tile finished: register epilogue (no smem, no barrier needed).
            const int mbase = (slot + (g >> 3) * nslot) * MTILE;
            const float* cv = g_cvec + a * EDIM;
#pragma unroll
            for (int mt = 0; mt < 2; mt++) {
                int r0 = mbase + m0 + mt * 16 + (lane >> 2);
#pragma unroll
                for (int nt = 0; nt < 8; nt++) {
                    int col = n0 + (nt >> 1) * 16 + (nt & 1) * 8 + (lane & 3) * 2;
                    float b0 = __ldg(cv + col);
                    float b1 = __ldg(cv + col + 1);
                    float2 v0 = make_float2(acc[mt][nt][0] + b0, acc[mt][nt][1] + b1);
                    float2 v1 = make_float2(acc[mt][nt][2] + b0, acc[mt][nt][3] + b1);
                    size_t base0 = (size_t)r0 * OUTSTRIDE + a * EDIM + col;
                    size_t base1 = (size_t)(r0 + 8) * OUTSTRIDE + a * EDIM + col;
                    *reinterpret_cast<float2*>(out + base0) = v0;
                    *reinterpret_cast<float2*>(out + base1) = v1;
                    acc[mt][nt][0] = 0.f; acc[mt][nt][1] = 0.f;
                    acc[mt][nt][2] = 0.f; acc[mt][nt][3] = 0.f;
                }
            }
        }
    }
}

extern "C" void kernel_launch(void* const* d_in, const int* in_sizes, int n_in,
                              void* d_out, int out_size) {
    const float* img  = (const float*)d_in[0];   // [B, E]
    const float* edge = (const float*)d_in[1];   // [B, A, E]
    const float* W    = (const float*)d_in[2];   // [E, 2E]
    const float* bvec = (const float*)d_in[3];   // [E]
    const float* proj = (const float*)d_in[4];   // [A, E, E]
    const int Bn = in_sizes[0] / EDIM;
    const int ntiles_m = Bn / MTILE;             // 512

    precompute_kernel<<<dim3(NUM_A, EDIM), 256>>>(W, bvec, proj);

    int sms = 148;
    cudaDeviceGetAttribute(&sms, cudaDevAttrMultiProcessorCount, 0);
    int nslot = (2 * sms) / NUM_A;               // 37 slots for 148 SMs
    if (nslot < 1) nslot = 1;
    if (nslot > ntiles_m) nslot = ntiles_m;

    cudaFuncSetAttribute(gnn_kernel, cudaFuncAttributeMaxDynamicSharedMemorySize, SMEM_TOTAL);
    // CTA (a, slot): slot-aligned m-tile sweeps keep the 8 a-CTAs of a slot on
    // the same img/edge rows concurrently for L2/DRAM locality.
    gnn_kernel<<<dim3(NUM_A, nslot), THREADS, SMEM_TOTAL>>>(img, edge, (float*)d_out, ntiles_m);
}